// round 6
// baseline (speedup 1.0000x reference)
#include <cuda_runtime.h>
#include <math.h>

#define HW 64
#define NP 4096
#define CHUNK 2048
#define MAXB 32

// scratch: [batch][arr(0=g,1=bnd)][4096] — two sorted ascending 2048-chunks per array
__device__ __align__(16) float g_scr[2 * MAXB * NP];
// monotonically-increasing grid-barrier ticket counter (never reset; graph-replay-safe)
__device__ unsigned int g_bar;

// 256-thread subgroup barrier (ids 1..4; id 0 reserved for __syncthreads)
__device__ __forceinline__ void group_bar(int t) {
    asm volatile("bar.sync %0, 256;" :: "r"((t >> 8) + 1) : "memory");
}

__global__ __launch_bounds__(1024, 1)
void chamfer_fused_kernel(const float* __restrict__ depth,
                          const float* __restrict__ bnd,
                          float* __restrict__ out,
                          float inv_total) {
    __shared__ float sm[2 * NP];   // sort: 2x2048 ping-pong; merge: 2x4096 ping-pong
    __shared__ float swarp[32];
    const int t   = threadIdx.x;
    const int blk = blockIdx.x;
    const int c   = blk & 1;          // chunk within array
    const int arr = (blk >> 1) & 1;   // 0 = sobel(g), 1 = boundary
    const int b   = blk >> 2;         // batch
    const unsigned int nblk = gridDim.x;

    if (blk == 0 && t == 0) out[0] = 0.0f;   // consumed only after grid barrier

    const int i  = 2 * t;             // element index within own chunk
    const int e0 = c * CHUNK + i;     // element index within batch array

    // ---- Phase 1: produce this block's 2048 values ----
    float v0, v1;
    if (arr == 1) {
        float2 q = *(const float2*)(bnd + b * NP + e0);
        v0 = q.x; v1 = q.y;
    } else {
        const float* d = depth + b * NP;
        #pragma unroll
        for (int m = 0; m < 2; m++) {
            int e = e0 + m;
            int y = e >> 6, x = e & 63;
            float p[3][3];
            #pragma unroll
            for (int dy = -1; dy <= 1; dy++)
                #pragma unroll
                for (int dx = -1; dx <= 1; dx++) {
                    int yy = y + dy, xx = x + dx;
                    bool ok = (yy >= 0) & (yy < HW) & (xx >= 0) & (xx < HW);
                    p[dy + 1][dx + 1] = ok ? d[yy * HW + xx] : 0.0f;
                }
            float gx = (p[0][0] - p[0][2]) + 2.0f * (p[1][0] - p[1][2]) + (p[2][0] - p[2][2]);
            float gy = (p[0][0] - p[2][0]) + 2.0f * (p[0][1] - p[2][1]) + (p[0][2] - p[2][2]);
            float g = sqrtf(gx * gx + gy * gy + 1e-8f);
            if (m == 0) v0 = g; else v1 = g;
        }
    }

    // ---- Phase 2: ascending bitonic sort of the 2048-chunk ----
    // j>=64: double-buffered smem (ONE barrier/step); j=2..32: shfl; j=1: in-thread.
    // Barrier span rule: barrier at a step must cover max(j, j_prev) -> full
    // __syncthreads only when (k>=1024 && j>=256); else 256-thread group bar.
    int pbuf = 0;
    #pragma unroll
    for (int k = 2; k <= CHUNK; k <<= 1) {
        #pragma unroll
        for (int j = k >> 1; j >= 1; j >>= 1) {
            if (j >= 64) {
                float* buf = sm + pbuf * CHUNK;
                *(float2*)&buf[i] = make_float2(v0, v1);
                if (k >= 1024 && j >= 256) __syncthreads(); else group_bar(t);
                bool keepMin = ((i & j) == 0) == ((i & k) == 0);
                float2 o = *(float2*)&buf[i ^ j];
                v0 = keepMin ? fminf(v0, o.x) : fmaxf(v0, o.x);
                v1 = keepMin ? fminf(v1, o.y) : fmaxf(v1, o.y);
                pbuf ^= 1;
            } else if (j >= 2) {
                bool keepMin = ((i & j) == 0) == ((i & k) == 0);
                float o0 = __shfl_xor_sync(0xffffffffu, v0, j >> 1);
                float o1 = __shfl_xor_sync(0xffffffffu, v1, j >> 1);
                v0 = keepMin ? fminf(v0, o0) : fmaxf(v0, o0);
                v1 = keepMin ? fminf(v1, o1) : fmaxf(v1, o1);
            } else {
                bool up = ((i & k) == 0);
                float lo = fminf(v0, v1), hi = fmaxf(v0, v1);
                v0 = up ? lo : hi;
                v1 = up ? hi : lo;
            }
        }
    }

    // publish sorted chunk (v0,v1 stay in registers as this block's queries)
    *(float2*)(g_scr + (b * 2 + arr) * NP + e0) = make_float2(v0, v1);

    // ---- Phase 3: grid barrier (ticket-based, replay-safe) ----
    __syncthreads();
    if (t == 0) {
        __threadfence();
        unsigned int ticket = atomicAdd(&g_bar, 1u);
        unsigned int target = (ticket / nblk + 1u) * nblk;
        while (*(volatile unsigned int*)&g_bar < target) { }
    }
    __syncthreads();
    __threadfence();

    // ---- Phase 4: merge the other array's two chunks into one sorted 4096 ----
    const float* tgt = g_scr + (b * 2 + (arr ^ 1)) * NP;
    const int idx = 4 * t;
    float w[4];
    if (idx < CHUNK) {                       // lower half: ascending as stored
        float4 q = *(const float4*)(tgt + idx);
        w[0] = q.x; w[1] = q.y; w[2] = q.z; w[3] = q.w;
    } else {                                 // upper half reversed -> descending
        float4 q = *(const float4*)(tgt + (6140 - idx));
        w[0] = q.w; w[1] = q.z; w[2] = q.y; w[3] = q.x;
    }
    // bitonic merge, k=4096 (ascending). smem for j>=128 (dbuf), shfl j=4..64,
    // in-thread j=2,1. Span rule: full sync when j>=512 (covers j_prev too).
    int mb = 0;
    #pragma unroll
    for (int j = 2048; j >= 128; j >>= 1) {
        float* buf = sm + mb * NP;
        *(float4*)&buf[idx] = make_float4(w[0], w[1], w[2], w[3]);
        if (j >= 512) __syncthreads(); else group_bar(t);
        bool keepMin = ((idx & j) == 0);
        float4 o = *(float4*)&buf[idx ^ j];
        w[0] = keepMin ? fminf(w[0], o.x) : fmaxf(w[0], o.x);
        w[1] = keepMin ? fminf(w[1], o.y) : fmaxf(w[1], o.y);
        w[2] = keepMin ? fminf(w[2], o.z) : fmaxf(w[2], o.z);
        w[3] = keepMin ? fminf(w[3], o.w) : fmaxf(w[3], o.w);
        mb ^= 1;
    }
    #pragma unroll
    for (int j = 64; j >= 4; j >>= 1) {
        bool keepMin = ((idx & j) == 0);
        #pragma unroll
        for (int m = 0; m < 4; m++) {
            float o = __shfl_xor_sync(0xffffffffu, w[m], j >> 2);
            w[m] = keepMin ? fminf(w[m], o) : fmaxf(w[m], o);
        }
    }
    {   // j = 2
        float lo0 = fminf(w[0], w[2]), hi0 = fmaxf(w[0], w[2]);
        float lo1 = fminf(w[1], w[3]), hi1 = fmaxf(w[1], w[3]);
        w[0] = lo0; w[2] = hi0; w[1] = lo1; w[3] = hi1;
    }
    {   // j = 1
        float lo = fminf(w[0], w[1]), hi = fmaxf(w[0], w[1]);
        w[0] = lo; w[1] = hi;
        lo = fminf(w[2], w[3]); hi = fmaxf(w[2], w[3]);
        w[2] = lo; w[3] = hi;
    }
    float* sT = sm + NP;   // buffer 1 (mb ended at 1; last reads of it covered by group bars)
    *(float4*)&sT[idx] = make_float4(w[0], w[1], w[2], w[3]);
    __syncthreads();

    // ---- Phase 5: single 12-deep search per query (queries sorted, in regs) ----
    float acc = 0.0f;
    #pragma unroll
    for (int m = 0; m < 2; m++) {
        float x = m ? v1 : v0;
        int pos = 0;                   // branchless lower_bound, saturates at NP-1
        #pragma unroll
        for (int s = NP / 2; s >= 1; s >>= 1) {
            if (sT[pos + s - 1] < x) pos += s;
        }
        // if x > all: pos=NP-1, sT[pos]<x, fabsf = distance to global max
        float dd = fabsf(sT[pos] - x);
        if (pos > 0) dd = fminf(dd, x - sT[pos - 1]);
        acc += dd;
    }

    // ---- Phase 6: reduce + accumulate ----
    #pragma unroll
    for (int o = 16; o > 0; o >>= 1) acc += __shfl_xor_sync(0xffffffffu, acc, o);
    if ((t & 31) == 0) swarp[t >> 5] = acc;
    __syncthreads();
    if (t < 32) {
        float z = swarp[t];            // exactly 32 warps
        #pragma unroll
        for (int o = 16; o > 0; o >>= 1) z += __shfl_xor_sync(0xffffffffu, z, o);
        if (t == 0) atomicAdd(out, z * inv_total);
    }
}

extern "C" void kernel_launch(void* const* d_in, const int* in_sizes, int n_in,
                              void* d_out, int out_size) {
    const float* depth = (const float*)d_in[0];
    const float* bnd   = (const float*)d_in[1];
    float* out = (float*)d_out;

    int B = in_sizes[0] / NP;
    if (B > MAXB) B = MAXB;
    float inv_total = 1.0f / (float)(B * NP);

    chamfer_fused_kernel<<<B * 4, 1024>>>(depth, bnd, out, inv_total);
}